// round 1
// baseline (speedup 1.0000x reference)
#include <cuda_runtime.h>
#include <math.h>

#define NN 50000
#define NE 800000
#define H  64
#define ND 128
#define NL 3

// ---- scratch (static device globals; no allocation) ----
__device__ float g_xb[2][NN * H];   // ping-pong node states
__device__ float g_e[NE * H];       // encoded edge features
__device__ float g_agg[NN * H];     // per-layer aggregation

// ============================================================
// Node encoder: x0 = nf @ W + b      [NN,128] x [128,64]
// block = 128 threads (4 warps), T=4 nodes per warp
// ============================================================
__global__ void k_enc_node(const float* __restrict__ nf,
                           const float* __restrict__ W,
                           const float* __restrict__ b) {
    __shared__ float Ws[ND * H];
    __shared__ float bs[H];
    __shared__ float ibuf[4][4 * ND];
    int tid = threadIdx.x;
    for (int i = tid; i < ND * H; i += blockDim.x) Ws[i] = W[i];
    if (tid < H) bs[tid] = b[tid];
    __syncthreads();
    int lane = tid & 31, wid = tid >> 5;
    float* win = ibuf[wid];
    int gw = blockIdx.x * 4 + wid;
    int nw = gridDim.x * 4;
    for (int base = gw * 4; base < NN; base += nw * 4) {
        #pragma unroll
        for (int t = 0; t < 4; t++) {
            const float* r = nf + (size_t)(base + t) * ND;
            win[t * ND + lane]      = r[lane];
            win[t * ND + lane + 32] = r[lane + 32];
            win[t * ND + lane + 64] = r[lane + 64];
            win[t * ND + lane + 96] = r[lane + 96];
        }
        __syncwarp();
        float a0[4], a1[4];
        #pragma unroll
        for (int t = 0; t < 4; t++) { a0[t] = bs[lane]; a1[t] = bs[lane + 32]; }
        #pragma unroll 4
        for (int k = 0; k < ND; k++) {
            float w0 = Ws[k * H + lane], w1 = Ws[k * H + lane + 32];
            #pragma unroll
            for (int t = 0; t < 4; t++) {
                float v = win[t * ND + k];
                a0[t] += v * w0; a1[t] += v * w1;
            }
        }
        #pragma unroll
        for (int t = 0; t < 4; t++) {
            g_xb[0][(size_t)(base + t) * H + lane]      = a0[t];
            g_xb[0][(size_t)(base + t) * H + lane + 32] = a1[t];
        }
        __syncwarp();
    }
}

// ============================================================
// Edge encoder: e = ef @ W + b       [NE,64] x [64,64]
// block = 256 threads (8 warps), T=4 edges per warp
// ============================================================
__global__ void k_enc_edge(const float* __restrict__ ef,
                           const float* __restrict__ W,
                           const float* __restrict__ b) {
    __shared__ float Ws[H * H];
    __shared__ float bs[H];
    __shared__ float ibuf[8][4 * H];
    int tid = threadIdx.x;
    for (int i = tid; i < H * H; i += blockDim.x) Ws[i] = W[i];
    if (tid < H) bs[tid] = b[tid];
    __syncthreads();
    int lane = tid & 31, wid = tid >> 5;
    float* win = ibuf[wid];
    int gw = blockIdx.x * 8 + wid;
    int nw = gridDim.x * 8;
    for (int base = gw * 4; base < NE; base += nw * 4) {
        #pragma unroll
        for (int t = 0; t < 4; t++) {
            const float* r = ef + (size_t)(base + t) * H;
            win[t * H + lane]      = r[lane];
            win[t * H + lane + 32] = r[lane + 32];
        }
        __syncwarp();
        float a0[4], a1[4];
        #pragma unroll
        for (int t = 0; t < 4; t++) { a0[t] = bs[lane]; a1[t] = bs[lane + 32]; }
        #pragma unroll 4
        for (int k = 0; k < H; k++) {
            float w0 = Ws[k * H + lane], w1 = Ws[k * H + lane + 32];
            #pragma unroll
            for (int t = 0; t < 4; t++) {
                float v = win[t * H + k];
                a0[t] += v * w0; a1[t] += v * w1;
            }
        }
        #pragma unroll
        for (int t = 0; t < 4; t++) {
            g_e[(size_t)(base + t) * H + lane]      = a0[t];
            g_e[(size_t)(base + t) * H + lane + 32] = a1[t];
        }
        __syncwarp();
    }
}

// ============================================================
// Zero the aggregation buffer
// ============================================================
__global__ void k_zero() {
    int i = blockIdx.x * blockDim.x + threadIdx.x;
    if (i < NN * H) g_agg[i] = 0.f;
}

// ============================================================
// Edge message MLP + scatter:
//   in = [x[src], e, x[dst]] (192) -> relu(W1) -> (64) -> W2 -> atomicAdd(agg[dst])
// dynamic smem; block 256 (8 warps), T=4 edges per warp
// ============================================================
__global__ void k_msg(const int* __restrict__ ei,
                      const float* __restrict__ W1, const float* __restrict__ b1,
                      const float* __restrict__ W2, const float* __restrict__ b2,
                      int si) {
    extern __shared__ float sm[];
    float* W1s = sm;                   // 192*64
    float* W2s = W1s + 192 * H;        // 64*64
    float* b1s = W2s + H * H;          // 64
    float* b2s = b1s + H;              // 64
    float* inb = b2s + H;              // 8*4*192
    float* hb  = inb + 8 * 4 * 192;    // 8*4*64

    int tid = threadIdx.x;
    for (int i = tid; i < 192 * H; i += blockDim.x) W1s[i] = W1[i];
    for (int i = tid; i < H * H; i += blockDim.x)   W2s[i] = W2[i];
    if (tid < H) { b1s[tid] = b1[tid]; b2s[tid] = b2[tid]; }
    __syncthreads();

    const float* x = g_xb[si];
    int lane = tid & 31, wid = tid >> 5;
    float* win = inb + wid * 4 * 192;
    float* wh  = hb  + wid * 4 * H;
    int gw = blockIdx.x * 8 + wid;
    int nw = gridDim.x * 8;
    const int* src = ei;
    const int* dst = ei + NE;

    for (int base = gw * 4; base < NE; base += nw * 4) {
        int d[4];
        #pragma unroll
        for (int t = 0; t < 4; t++) {
            int e = base + t;
            int s = __ldg(src + e);
            d[t]  = __ldg(dst + e);
            win[t * 192 + lane]       = __ldg(x + (size_t)s * H + lane);
            win[t * 192 + lane + 32]  = __ldg(x + (size_t)s * H + lane + 32);
            win[t * 192 + 64 + lane]      = g_e[(size_t)e * H + lane];
            win[t * 192 + 64 + lane + 32] = g_e[(size_t)e * H + lane + 32];
            win[t * 192 + 128 + lane]      = __ldg(x + (size_t)d[t] * H + lane);
            win[t * 192 + 128 + lane + 32] = __ldg(x + (size_t)d[t] * H + lane + 32);
        }
        __syncwarp();

        float a0[4], a1[4];
        #pragma unroll
        for (int t = 0; t < 4; t++) { a0[t] = b1s[lane]; a1[t] = b1s[lane + 32]; }
        #pragma unroll 4
        for (int k = 0; k < 192; k++) {
            float w0 = W1s[k * H + lane], w1 = W1s[k * H + lane + 32];
            #pragma unroll
            for (int t = 0; t < 4; t++) {
                float v = win[t * 192 + k];
                a0[t] += v * w0; a1[t] += v * w1;
            }
        }
        #pragma unroll
        for (int t = 0; t < 4; t++) {
            wh[t * H + lane]      = fmaxf(a0[t], 0.f);
            wh[t * H + lane + 32] = fmaxf(a1[t], 0.f);
        }
        __syncwarp();

        float c0[4], c1[4];
        #pragma unroll
        for (int t = 0; t < 4; t++) { c0[t] = b2s[lane]; c1[t] = b2s[lane + 32]; }
        #pragma unroll 4
        for (int k = 0; k < H; k++) {
            float w0 = W2s[k * H + lane], w1 = W2s[k * H + lane + 32];
            #pragma unroll
            for (int t = 0; t < 4; t++) {
                float v = wh[t * H + k];
                c0[t] += v * w0; c1[t] += v * w1;
            }
        }
        #pragma unroll
        for (int t = 0; t < 4; t++) {
            atomicAdd(&g_agg[(size_t)d[t] * H + lane],      c0[t]);
            atomicAdd(&g_agg[(size_t)d[t] * H + lane + 32], c1[t]);
        }
        __syncwarp();
    }
}

// ============================================================
// Node update MLP: in = [x, agg] (128) -> relu(W1) -> W2 -> x'
// ============================================================
__global__ void k_upd(const float* __restrict__ W1, const float* __restrict__ b1,
                      const float* __restrict__ W2, const float* __restrict__ b2,
                      int si, int di) {
    extern __shared__ float sm[];
    float* W1s = sm;                   // 128*64
    float* W2s = W1s + ND * H;         // 64*64
    float* b1s = W2s + H * H;
    float* b2s = b1s + H;
    float* inb = b2s + H;              // 8*4*128
    float* hb  = inb + 8 * 4 * ND;     // 8*4*64

    int tid = threadIdx.x;
    for (int i = tid; i < ND * H; i += blockDim.x) W1s[i] = W1[i];
    for (int i = tid; i < H * H; i += blockDim.x)  W2s[i] = W2[i];
    if (tid < H) { b1s[tid] = b1[tid]; b2s[tid] = b2[tid]; }
    __syncthreads();

    const float* xs = g_xb[si];
    float* xd = g_xb[di];
    int lane = tid & 31, wid = tid >> 5;
    float* win = inb + wid * 4 * ND;
    float* wh  = hb  + wid * 4 * H;
    int gw = blockIdx.x * 8 + wid;
    int nw = gridDim.x * 8;

    for (int base = gw * 4; base < NN; base += nw * 4) {
        #pragma unroll
        for (int t = 0; t < 4; t++) {
            int n = base + t;
            win[t * ND + lane]           = xs[(size_t)n * H + lane];
            win[t * ND + lane + 32]      = xs[(size_t)n * H + lane + 32];
            win[t * ND + 64 + lane]      = g_agg[(size_t)n * H + lane];
            win[t * ND + 64 + lane + 32] = g_agg[(size_t)n * H + lane + 32];
        }
        __syncwarp();

        float a0[4], a1[4];
        #pragma unroll
        for (int t = 0; t < 4; t++) { a0[t] = b1s[lane]; a1[t] = b1s[lane + 32]; }
        #pragma unroll 4
        for (int k = 0; k < ND; k++) {
            float w0 = W1s[k * H + lane], w1 = W1s[k * H + lane + 32];
            #pragma unroll
            for (int t = 0; t < 4; t++) {
                float v = win[t * ND + k];
                a0[t] += v * w0; a1[t] += v * w1;
            }
        }
        #pragma unroll
        for (int t = 0; t < 4; t++) {
            wh[t * H + lane]      = fmaxf(a0[t], 0.f);
            wh[t * H + lane + 32] = fmaxf(a1[t], 0.f);
        }
        __syncwarp();

        float c0[4], c1[4];
        #pragma unroll
        for (int t = 0; t < 4; t++) { c0[t] = b2s[lane]; c1[t] = b2s[lane + 32]; }
        #pragma unroll 4
        for (int k = 0; k < H; k++) {
            float w0 = W2s[k * H + lane], w1 = W2s[k * H + lane + 32];
            #pragma unroll
            for (int t = 0; t < 4; t++) {
                float v = wh[t * H + k];
                c0[t] += v * w0; c1[t] += v * w1;
            }
        }
        #pragma unroll
        for (int t = 0; t < 4; t++) {
            xd[(size_t)(base + t) * H + lane]      = c0[t];
            xd[(size_t)(base + t) * H + lane + 32] = c1[t];
        }
        __syncwarp();
    }
}

// ============================================================
// Constraints head + output writeback
//   out[0 .. NN*H)        = x
//   out[NN*H .. NN*H+NN)  = sigmoid(relu(x@W1+b1)@w2 + b2)
// ============================================================
__global__ void k_con(const float* __restrict__ W1, const float* __restrict__ b1,
                      const float* __restrict__ w2, const float* __restrict__ b2,
                      int si, float* __restrict__ out) {
    __shared__ float Ws[H * H];
    __shared__ float bs[H];
    __shared__ float w2s[H];
    __shared__ float xb[8][H];
    __shared__ float b2v;
    int tid = threadIdx.x;
    for (int i = tid; i < H * H; i += blockDim.x) Ws[i] = W1[i];
    if (tid < H) { bs[tid] = b1[tid]; w2s[tid] = w2[tid]; }
    if (tid == 0) b2v = b2[0];
    __syncthreads();

    const float* xs = g_xb[si];
    int lane = tid & 31, wid = tid >> 5;
    int gw = blockIdx.x * 8 + wid;
    int nw = gridDim.x * 8;
    for (int n = gw; n < NN; n += nw) {
        float xv0 = xs[(size_t)n * H + lane];
        float xv1 = xs[(size_t)n * H + lane + 32];
        out[(size_t)n * H + lane]      = xv0;
        out[(size_t)n * H + lane + 32] = xv1;
        xb[wid][lane]      = xv0;
        xb[wid][lane + 32] = xv1;
        __syncwarp();
        float a0 = bs[lane], a1 = bs[lane + 32];
        #pragma unroll 4
        for (int k = 0; k < H; k++) {
            float v = xb[wid][k];
            a0 += v * Ws[k * H + lane];
            a1 += v * Ws[k * H + lane + 32];
        }
        float p = fmaxf(a0, 0.f) * w2s[lane] + fmaxf(a1, 0.f) * w2s[lane + 32];
        #pragma unroll
        for (int o = 16; o; o >>= 1) p += __shfl_xor_sync(0xffffffffu, p, o);
        if (lane == 0)
            out[(size_t)NN * H + n] = 1.f / (1.f + expf(-(p + b2v)));
        __syncwarp();
    }
}

// ============================================================
// Launcher
// ============================================================
extern "C" void kernel_launch(void* const* d_in, const int* in_sizes, int n_in,
                              void* d_out, int out_size) {
    const float* nf  = (const float*)d_in[0];
    const float* ef  = (const float*)d_in[1];
    const int*   ei  = (const int*)d_in[2];
    const float* enW = (const float*)d_in[3];
    const float* enb = (const float*)d_in[4];
    const float* eeW = (const float*)d_in[5];
    const float* eeb = (const float*)d_in[6];
    const float* mW1 = (const float*)d_in[7];
    const float* mb1 = (const float*)d_in[8];
    const float* mW2 = (const float*)d_in[9];
    const float* mb2 = (const float*)d_in[10];
    const float* uW1 = (const float*)d_in[11];
    const float* ub1 = (const float*)d_in[12];
    const float* uW2 = (const float*)d_in[13];
    const float* ub2 = (const float*)d_in[14];
    const float* cW1 = (const float*)d_in[15];
    const float* cb1 = (const float*)d_in[16];
    const float* cW2 = (const float*)d_in[17];
    const float* cb2 = (const float*)d_in[18];
    float* out = (float*)d_out;

    const int MSG_SMEM = (192 * H + H * H + 2 * H + 8 * 4 * 192 + 8 * 4 * H) * 4; // 98816
    const int UPD_SMEM = (ND * H + H * H + 2 * H + 8 * 4 * ND + 8 * 4 * H) * 4;   // 74240
    cudaFuncSetAttribute(k_msg, cudaFuncAttributeMaxDynamicSharedMemorySize, MSG_SMEM);
    cudaFuncSetAttribute(k_upd, cudaFuncAttributeMaxDynamicSharedMemorySize, UPD_SMEM);

    k_enc_node<<<1184, 128>>>(nf, enW, enb);
    k_enc_edge<<<1184, 256>>>(ef, eeW, eeb);

    int cur = 0;
    for (int l = 0; l < NL; l++) {
        k_zero<<<(NN * H + 255) / 256, 256>>>();
        k_msg<<<296, 256, MSG_SMEM>>>(ei,
                                      mW1 + (size_t)l * 192 * H, mb1 + l * H,
                                      mW2 + (size_t)l * H * H,   mb2 + l * H,
                                      cur);
        k_upd<<<296, 256, UPD_SMEM>>>(uW1 + (size_t)l * ND * H, ub1 + l * H,
                                      uW2 + (size_t)l * H * H,  ub2 + l * H,
                                      cur, 1 - cur);
        cur = 1 - cur;
    }
    k_con<<<1184, 256>>>(cW1, cb1, cW2, cb2, cur, out);
}

// round 2
// speedup vs baseline: 1.2158x; 1.2158x over previous
#include <cuda_runtime.h>
#include <math.h>

#define NN 50000
#define NE 800000
#define H  64

// ---- scratch (static device globals; no allocation) ----
__device__ float g_xb[2][NN * H];   // ping-pong node states
__device__ float g_e[NE * H];       // encoded edge features
__device__ float g_agg[NN * H];     // per-layer aggregation

typedef unsigned long long ull;

// packed fp32 FMA: d.lo += a.lo*b.lo ; d.hi += a.hi*b.hi
__device__ __forceinline__ void ffma2(ull& d, ull a, ull b) {
    asm("fma.rn.f32x2 %0, %1, %2, %0;" : "+l"(d) : "l"(a), "l"(b));
}
// fold K-parity partial sums + bias
__device__ __forceinline__ float fin(ull a, float b) {
    float lo = __uint_as_float((unsigned)a);
    float hi = __uint_as_float((unsigned)(a >> 32));
    return lo + hi + b;
}

// ============================================================
// Edge message MLP + scatter (the hot kernel)
//   in = [x[src], e, x[dst]] (192) -> relu(W1) -> W2 -> atomicAdd(agg[dst])
// block 256 (8 warps), T=8 edges per warp, f32x2 K-parity accumulation.
// Weight smem layout: per lane (covers cols 2l, 2l+1), per k-pair:
//   16B = {W[k0][c0], W[k1][c0], W[k0][c1], W[k1][c1]}
// lane stride padded (+4 words) -> conflict-free LDS.128.
// ============================================================
__global__ void __launch_bounds__(256) k_msg(const int* __restrict__ ei,
        const float* __restrict__ W1, const float* __restrict__ b1,
        const float* __restrict__ W2, const float* __restrict__ b2, int si) {
    extern __shared__ float sm[];
    float* W1p  = sm;                 // 32 * 388 = 12416
    float* W2p  = W1p + 12416;        // 32 * 132 = 4224
    float* winb = W2p + 4224;         // 8w * 8t * 192 = 12288
    float* hbb  = winb + 12288;       // 8w * 8t * 64  = 4096
    int tid = threadIdx.x;
    for (int i = tid; i < 192 * 64; i += 256) {
        int k = i >> 6, c = i & 63;
        W1p[(c >> 1) * 388 + (k >> 1) * 4 + ((c & 1) << 1) + (k & 1)] = W1[i];
    }
    for (int i = tid; i < 64 * 64; i += 256) {
        int k = i >> 6, c = i & 63;
        W2p[(c >> 1) * 132 + (k >> 1) * 4 + ((c & 1) << 1) + (k & 1)] = W2[i];
    }
    __syncthreads();

    int lane = tid & 31, wid = tid >> 5;
    float2 bb1 = ((const float2*)b1)[lane];
    float2 bb2 = ((const float2*)b2)[lane];
    float* win = winb + wid * 8 * 192;
    float* hb  = hbb  + wid * 8 * 64;
    const float* x = g_xb[si];
    const int* src = ei;
    const int* dst = ei + NE;
    const ulonglong2* w1l = (const ulonglong2*)(W1p + (size_t)lane * 388);
    const ulonglong2* w2l = (const ulonglong2*)(W2p + (size_t)lane * 132);
    int li = lane & 15, half = lane >> 4;

    int gw = blockIdx.x * 8 + wid;
    int nw = gridDim.x * 8;
    for (int base = gw * 8; base < NE; base += nw * 8) {
        // ---- stage 8 edges: [x[src] | e | x[dst]] into win ----
        int d8[8];
        #pragma unroll
        for (int t = 0; t < 8; t++) {
            int e = base + t;
            int s = __ldg(src + e);
            int d = __ldg(dst + e);
            d8[t] = d;
            const float* row = x + (size_t)(half ? d : s) * H;
            float4 v = *(const float4*)(row + li * 4);
            *(float4*)(win + t * 192 + half * 128 + li * 4) = v;
        }
        #pragma unroll
        for (int tp = 0; tp < 4; tp++) {
            int t = tp * 2 + half;
            float4 v = *(const float4*)(g_e + (size_t)(base + t) * H + li * 4);
            *(float4*)(win + t * 192 + 64 + li * 4) = v;
        }
        __syncwarp();

        // ---- layer 1: 192 -> 64, relu ----
        ull a0[8], a1[8];
        #pragma unroll
        for (int t = 0; t < 8; t++) { a0[t] = 0ull; a1[t] = 0ull; }
        #pragma unroll 4
        for (int c = 0; c < 48; c++) {           // 48 chunks of 4 k
            ulonglong2 wA = w1l[2 * c];
            ulonglong2 wB = w1l[2 * c + 1];
            #pragma unroll
            for (int t = 0; t < 8; t++) {
                ulonglong2 v = ((const ulonglong2*)(win + t * 192))[c];
                ffma2(a0[t], wA.x, v.x);
                ffma2(a1[t], wA.y, v.x);
                ffma2(a0[t], wB.x, v.y);
                ffma2(a1[t], wB.y, v.y);
            }
        }
        #pragma unroll
        for (int t = 0; t < 8; t++) {
            float h0 = fmaxf(fin(a0[t], bb1.x), 0.f);
            float h1 = fmaxf(fin(a1[t], bb1.y), 0.f);
            *(float2*)(hb + t * 64 + 2 * lane) = make_float2(h0, h1);
        }
        __syncwarp();

        // ---- layer 2: 64 -> 64 ----
        ull c0[8], c1[8];
        #pragma unroll
        for (int t = 0; t < 8; t++) { c0[t] = 0ull; c1[t] = 0ull; }
        #pragma unroll
        for (int c = 0; c < 16; c++) {
            ulonglong2 wA = w2l[2 * c];
            ulonglong2 wB = w2l[2 * c + 1];
            #pragma unroll
            for (int t = 0; t < 8; t++) {
                ulonglong2 v = ((const ulonglong2*)(hb + t * 64))[c];
                ffma2(c0[t], wA.x, v.x);
                ffma2(c1[t], wA.y, v.x);
                ffma2(c0[t], wB.x, v.y);
                ffma2(c1[t], wB.y, v.y);
            }
        }
        #pragma unroll
        for (int t = 0; t < 8; t++) {
            float o0 = fin(c0[t], bb2.x);
            float o1 = fin(c1[t], bb2.y);
            float* p = g_agg + (size_t)d8[t] * H + 2 * lane;
            atomicAdd(p, o0);
            atomicAdd(p + 1, o1);
        }
        __syncwarp();
    }
}

// ============================================================
// Node update MLP: in = [x, agg] (128) -> relu(W1) -> W2 -> x'
// ============================================================
__global__ void __launch_bounds__(256) k_upd(
        const float* __restrict__ W1, const float* __restrict__ b1,
        const float* __restrict__ W2, const float* __restrict__ b2,
        int si, int di) {
    extern __shared__ float sm[];
    float* W1p  = sm;                 // 32 * 260 = 8320
    float* W2p  = W1p + 8320;         // 4224
    float* winb = W2p + 4224;         // 8w * 8t * 128 = 8192
    float* hbb  = winb + 8192;        // 4096
    int tid = threadIdx.x;
    for (int i = tid; i < 128 * 64; i += 256) {
        int k = i >> 6, c = i & 63;
        W1p[(c >> 1) * 260 + (k >> 1) * 4 + ((c & 1) << 1) + (k & 1)] = W1[i];
    }
    for (int i = tid; i < 64 * 64; i += 256) {
        int k = i >> 6, c = i & 63;
        W2p[(c >> 1) * 132 + (k >> 1) * 4 + ((c & 1) << 1) + (k & 1)] = W2[i];
    }
    __syncthreads();

    int lane = tid & 31, wid = tid >> 5;
    float2 bb1 = ((const float2*)b1)[lane];
    float2 bb2 = ((const float2*)b2)[lane];
    float* win = winb + wid * 8 * 128;
    float* hb  = hbb  + wid * 8 * 64;
    const float* xs = g_xb[si];
    float* xd = g_xb[di];
    const ulonglong2* w1l = (const ulonglong2*)(W1p + (size_t)lane * 260);
    const ulonglong2* w2l = (const ulonglong2*)(W2p + (size_t)lane * 132);
    int li = lane & 15, half = lane >> 4;

    int gw = blockIdx.x * 8 + wid;
    int nw = gridDim.x * 8;
    for (int base = gw * 8; base < NN; base += nw * 8) {
        #pragma unroll
        for (int t = 0; t < 8; t++) {
            int n = base + t;
            const float* row = half ? (g_agg + (size_t)n * H) : (xs + (size_t)n * H);
            float4 v = *(const float4*)(row + li * 4);
            *(float4*)(win + t * 128 + half * 64 + li * 4) = v;
        }
        __syncwarp();

        ull a0[8], a1[8];
        #pragma unroll
        for (int t = 0; t < 8; t++) { a0[t] = 0ull; a1[t] = 0ull; }
        #pragma unroll 4
        for (int c = 0; c < 32; c++) {
            ulonglong2 wA = w1l[2 * c];
            ulonglong2 wB = w1l[2 * c + 1];
            #pragma unroll
            for (int t = 0; t < 8; t++) {
                ulonglong2 v = ((const ulonglong2*)(win + t * 128))[c];
                ffma2(a0[t], wA.x, v.x);
                ffma2(a1[t], wA.y, v.x);
                ffma2(a0[t], wB.x, v.y);
                ffma2(a1[t], wB.y, v.y);
            }
        }
        #pragma unroll
        for (int t = 0; t < 8; t++) {
            float h0 = fmaxf(fin(a0[t], bb1.x), 0.f);
            float h1 = fmaxf(fin(a1[t], bb1.y), 0.f);
            *(float2*)(hb + t * 64 + 2 * lane) = make_float2(h0, h1);
        }
        __syncwarp();

        ull c0[8], c1[8];
        #pragma unroll
        for (int t = 0; t < 8; t++) { c0[t] = 0ull; c1[t] = 0ull; }
        #pragma unroll
        for (int c = 0; c < 16; c++) {
            ulonglong2 wA = w2l[2 * c];
            ulonglong2 wB = w2l[2 * c + 1];
            #pragma unroll
            for (int t = 0; t < 8; t++) {
                ulonglong2 v = ((const ulonglong2*)(hb + t * 64))[c];
                ffma2(c0[t], wA.x, v.x);
                ffma2(c1[t], wA.y, v.x);
                ffma2(c0[t], wB.x, v.y);
                ffma2(c1[t], wB.y, v.y);
            }
        }
        #pragma unroll
        for (int t = 0; t < 8; t++) {
            float o0 = fin(c0[t], bb2.x);
            float o1 = fin(c1[t], bb2.y);
            *(float2*)(xd + (size_t)(base + t) * H + 2 * lane) = make_float2(o0, o1);
        }
        __syncwarp();
    }
}

// ============================================================
// Node encoder: x0 = nf @ W + b    [NN,128] x [128,64]
// ============================================================
__global__ void __launch_bounds__(256) k_enc_node(const float* __restrict__ nf,
        const float* __restrict__ W, const float* __restrict__ b) {
    extern __shared__ float sm[];
    float* Wp   = sm;                 // 8320
    float* winb = Wp + 8320;          // 8192
    int tid = threadIdx.x;
    for (int i = tid; i < 128 * 64; i += 256) {
        int k = i >> 6, c = i & 63;
        Wp[(c >> 1) * 260 + (k >> 1) * 4 + ((c & 1) << 1) + (k & 1)] = W[i];
    }
    __syncthreads();

    int lane = tid & 31, wid = tid >> 5;
    float2 bb = ((const float2*)b)[lane];
    float* win = winb + wid * 8 * 128;
    const ulonglong2* wl = (const ulonglong2*)(Wp + (size_t)lane * 260);

    int gw = blockIdx.x * 8 + wid;
    int nw = gridDim.x * 8;
    for (int base = gw * 8; base < NN; base += nw * 8) {
        #pragma unroll
        for (int t = 0; t < 8; t++) {
            float4 v = *(const float4*)(nf + (size_t)(base + t) * 128 + lane * 4);
            *(float4*)(win + t * 128 + lane * 4) = v;
        }
        __syncwarp();
        ull a0[8], a1[8];
        #pragma unroll
        for (int t = 0; t < 8; t++) { a0[t] = 0ull; a1[t] = 0ull; }
        #pragma unroll 4
        for (int c = 0; c < 32; c++) {
            ulonglong2 wA = wl[2 * c];
            ulonglong2 wB = wl[2 * c + 1];
            #pragma unroll
            for (int t = 0; t < 8; t++) {
                ulonglong2 v = ((const ulonglong2*)(win + t * 128))[c];
                ffma2(a0[t], wA.x, v.x);
                ffma2(a1[t], wA.y, v.x);
                ffma2(a0[t], wB.x, v.y);
                ffma2(a1[t], wB.y, v.y);
            }
        }
        #pragma unroll
        for (int t = 0; t < 8; t++) {
            float o0 = fin(a0[t], bb.x);
            float o1 = fin(a1[t], bb.y);
            *(float2*)(g_xb[0] + (size_t)(base + t) * H + 2 * lane) = make_float2(o0, o1);
        }
        __syncwarp();
    }
}

// ============================================================
// Edge encoder: e = ef @ W + b     [NE,64] x [64,64]
// ============================================================
__global__ void __launch_bounds__(256) k_enc_edge(const float* __restrict__ ef,
        const float* __restrict__ W, const float* __restrict__ b) {
    extern __shared__ float sm[];
    float* Wp   = sm;                 // 4224
    float* winb = Wp + 4224;          // 8w * 8t * 64 = 4096
    int tid = threadIdx.x;
    for (int i = tid; i < 64 * 64; i += 256) {
        int k = i >> 6, c = i & 63;
        Wp[(c >> 1) * 132 + (k >> 1) * 4 + ((c & 1) << 1) + (k & 1)] = W[i];
    }
    __syncthreads();

    int lane = tid & 31, wid = tid >> 5;
    float2 bb = ((const float2*)b)[lane];
    float* win = winb + wid * 8 * 64;
    const ulonglong2* wl = (const ulonglong2*)(Wp + (size_t)lane * 132);
    int li = lane & 15, half = lane >> 4;

    int gw = blockIdx.x * 8 + wid;
    int nw = gridDim.x * 8;
    for (int base = gw * 8; base < NE; base += nw * 8) {
        #pragma unroll
        for (int tp = 0; tp < 4; tp++) {
            int t = tp * 2 + half;
            float4 v = *(const float4*)(ef + (size_t)(base + t) * H + li * 4);
            *(float4*)(win + t * 64 + li * 4) = v;
        }
        __syncwarp();
        ull a0[8], a1[8];
        #pragma unroll
        for (int t = 0; t < 8; t++) { a0[t] = 0ull; a1[t] = 0ull; }
        #pragma unroll
        for (int c = 0; c < 16; c++) {
            ulonglong2 wA = wl[2 * c];
            ulonglong2 wB = wl[2 * c + 1];
            #pragma unroll
            for (int t = 0; t < 8; t++) {
                ulonglong2 v = ((const ulonglong2*)(win + t * 64))[c];
                ffma2(a0[t], wA.x, v.x);
                ffma2(a1[t], wA.y, v.x);
                ffma2(a0[t], wB.x, v.y);
                ffma2(a1[t], wB.y, v.y);
            }
        }
        #pragma unroll
        for (int t = 0; t < 8; t++) {
            float o0 = fin(a0[t], bb.x);
            float o1 = fin(a1[t], bb.y);
            *(float2*)(g_e + (size_t)(base + t) * H + 2 * lane) = make_float2(o0, o1);
        }
        __syncwarp();
    }
}

// ============================================================
// Zero the aggregation buffer
// ============================================================
__global__ void k_zero() {
    int i = blockIdx.x * blockDim.x + threadIdx.x;
    if (i < NN * H) g_agg[i] = 0.f;
}

// ============================================================
// Constraints head + output writeback
// ============================================================
__global__ void k_con(const float* __restrict__ W1, const float* __restrict__ b1,
                      const float* __restrict__ w2, const float* __restrict__ b2,
                      int si, float* __restrict__ out) {
    __shared__ float Ws[H * H];
    __shared__ float bs[H];
    __shared__ float w2s[H];
    __shared__ float xb[8][H];
    __shared__ float b2v;
    int tid = threadIdx.x;
    for (int i = tid; i < H * H; i += blockDim.x) Ws[i] = W1[i];
    if (tid < H) { bs[tid] = b1[tid]; w2s[tid] = w2[tid]; }
    if (tid == 0) b2v = b2[0];
    __syncthreads();

    const float* xs = g_xb[si];
    int lane = tid & 31, wid = tid >> 5;
    int gw = blockIdx.x * 8 + wid;
    int nw = gridDim.x * 8;
    for (int n = gw; n < NN; n += nw) {
        float xv0 = xs[(size_t)n * H + lane];
        float xv1 = xs[(size_t)n * H + lane + 32];
        out[(size_t)n * H + lane]      = xv0;
        out[(size_t)n * H + lane + 32] = xv1;
        xb[wid][lane]      = xv0;
        xb[wid][lane + 32] = xv1;
        __syncwarp();
        float a0 = bs[lane], a1 = bs[lane + 32];
        #pragma unroll 4
        for (int k = 0; k < H; k++) {
            float v = xb[wid][k];
            a0 += v * Ws[k * H + lane];
            a1 += v * Ws[k * H + lane + 32];
        }
        float p = fmaxf(a0, 0.f) * w2s[lane] + fmaxf(a1, 0.f) * w2s[lane + 32];
        #pragma unroll
        for (int o = 16; o; o >>= 1) p += __shfl_xor_sync(0xffffffffu, p, o);
        if (lane == 0)
            out[(size_t)NN * H + n] = 1.f / (1.f + expf(-(p + b2v)));
        __syncwarp();
    }
}

// ============================================================
// Launcher
// ============================================================
extern "C" void kernel_launch(void* const* d_in, const int* in_sizes, int n_in,
                              void* d_out, int out_size) {
    const float* nf  = (const float*)d_in[0];
    const float* ef  = (const float*)d_in[1];
    const int*   ei  = (const int*)d_in[2];
    const float* enW = (const float*)d_in[3];
    const float* enb = (const float*)d_in[4];
    const float* eeW = (const float*)d_in[5];
    const float* eeb = (const float*)d_in[6];
    const float* mW1 = (const float*)d_in[7];
    const float* mb1 = (const float*)d_in[8];
    const float* mW2 = (const float*)d_in[9];
    const float* mb2 = (const float*)d_in[10];
    const float* uW1 = (const float*)d_in[11];
    const float* ub1 = (const float*)d_in[12];
    const float* uW2 = (const float*)d_in[13];
    const float* ub2 = (const float*)d_in[14];
    const float* cW1 = (const float*)d_in[15];
    const float* cb1 = (const float*)d_in[16];
    const float* cW2 = (const float*)d_in[17];
    const float* cb2 = (const float*)d_in[18];
    float* out = (float*)d_out;

    int dev = 0, smc = 148;
    cudaGetDevice(&dev);
    cudaDeviceGetAttribute(&smc, cudaDevAttrMultiProcessorCount, dev);

    const int MSG_SMEM = (12416 + 4224 + 12288 + 4096) * 4;  // 132096
    const int UPD_SMEM = (8320 + 4224 + 8192 + 4096) * 4;    // 99328
    const int ENN_SMEM = (8320 + 8192) * 4;                  // 66048
    const int ENE_SMEM = (4224 + 4096) * 4;                  // 33280
    cudaFuncSetAttribute(k_msg,      cudaFuncAttributeMaxDynamicSharedMemorySize, MSG_SMEM);
    cudaFuncSetAttribute(k_upd,      cudaFuncAttributeMaxDynamicSharedMemorySize, UPD_SMEM);
    cudaFuncSetAttribute(k_enc_node, cudaFuncAttributeMaxDynamicSharedMemorySize, ENN_SMEM);
    cudaFuncSetAttribute(k_enc_edge, cudaFuncAttributeMaxDynamicSharedMemorySize, ENE_SMEM);

    k_enc_node<<<smc * 2, 256, ENN_SMEM>>>(nf, enW, enb);
    k_enc_edge<<<smc * 4, 256, ENE_SMEM>>>(ef, eeW, eeb);

    int cur = 0;
    for (int l = 0; l < 3; l++) {
        k_zero<<<(NN * H + 255) / 256, 256>>>();
        k_msg<<<smc, 256, MSG_SMEM>>>(ei,
                                      mW1 + (size_t)l * 192 * H, mb1 + l * H,
                                      mW2 + (size_t)l * H * H,   mb2 + l * H,
                                      cur);
        k_upd<<<smc * 2, 256, UPD_SMEM>>>(uW1 + (size_t)l * 128 * H, ub1 + l * H,
                                          uW2 + (size_t)l * H * H,   ub2 + l * H,
                                          cur, 1 - cur);
        cur = 1 - cur;
    }
    k_con<<<1184, 256>>>(cW1, cb1, cW2, cb2, cur, out);
}